// round 2
// baseline (speedup 1.0000x reference)
#include <cuda_runtime.h>
#include <cuda_fp16.h>
#include <cstdint>
#include <math.h>

// ---------------- problem dims ----------------
#define Hdim 2048
#define Vdim 32000
#define Bdim 8
#define Tdim 256
#define Rdim (Bdim*Tdim)          // 2048 token rows
#define TILE_M 128
#define TILE_N 128
#define KC 64                     // halves per K chunk (128 bytes per row)
#define NUM_KC (Hdim/KC)          // 32
#define NUM_RT (Rdim/TILE_M)      // 16
#define NUM_VT (Vdim/TILE_N)      // 250
#define A_BYTES (TILE_M*KC*2)     // 16384
#define B_BYTES (TILE_N*KC*2)     // 16384
#define STAGE_BYTES (A_BYTES+B_BYTES)   // 32768
#define STAGES 3
#define SCRATCH_BYTES 8192
#define SMEM_TOTAL (STAGES*STAGE_BYTES + SCRATCH_BYTES)  // 106496

#define DINLINE __device__ __forceinline__

// ---------------- device scratch (no runtime alloc allowed) ----------------
__device__ __half g_x16 [(size_t)Rdim*Hdim];
__device__ __half g_rx16[(size_t)Rdim*Hdim];
__device__ __half g_w16 [(size_t)Vdim*Hdim];
__device__ __half g_rw16[(size_t)Vdim*Hdim];

struct Partial { float m1, s, m2; int c1, c2; };           // policy per (vt,row)
__device__ Partial g_part [NUM_VT][Rdim];
__device__ float2  g_rpart[NUM_VT][Rdim];                  // ref (rm, rs)
__device__ float   g_kl[Rdim];

// ---------------- helpers ----------------
DINLINE uint32_t smem_to_u32(const void* p) {
    uint32_t a;
    asm("{ .reg .u64 t; cvta.to.shared.u64 t, %1; cvt.u32.u64 %0, t; }" : "=r"(a) : "l"(p));
    return a;
}
DINLINE uint32_t lds_u32(uint32_t addr) {
    uint32_t v;
    asm volatile("ld.shared.b32 %0, [%1];" : "=r"(v) : "r"(addr));
    return v;
}
DINLINE void cp_async16(uint32_t saddr, const void* g) {
    asm volatile("cp.async.cg.shared.global [%0], [%1], 16;" :: "r"(saddr), "l"(g) : "memory");
}
#define CP_COMMIT() asm volatile("cp.async.commit_group;" ::: "memory")
#define SMEM_SWZ(off) ((off) ^ (((off) >> 3) & 0x70))

DINLINE void mma16816(float* d, uint32_t a0, uint32_t a1, uint32_t a2, uint32_t a3,
                      uint32_t b0, uint32_t b1) {
    asm volatile(
        "mma.sync.aligned.m16n8k16.row.col.f32.f16.f16.f32 "
        "{%0,%1,%2,%3}, {%4,%5,%6,%7}, {%8,%9}, {%0,%1,%2,%3};"
        : "+f"(d[0]), "+f"(d[1]), "+f"(d[2]), "+f"(d[3])
        : "r"(a0), "r"(a1), "r"(a2), "r"(a3), "r"(b0), "r"(b1));
}

// merge two (top2 + relative sumexp) sets; "self" wins ties (lower column first)
DINLINE void comb(float& m1, int& c1, float& m2, int& c2, float& s,
                  float om1, int oc1, float om2, int oc2, float os) {
    float M = fmaxf(m1, om1);
    s = s * __expf(m1 - M) + os * __expf(om1 - M);
    float n1, n2; int k1, k2;
    if (m1 >= om1) { n1 = m1; k1 = c1; if (om1 > m2) { n2 = om1; k2 = oc1; } else { n2 = m2; k2 = c2; } }
    else           { n1 = om1; k1 = oc1; if (m1 > om2) { n2 = m1; k2 = c1; } else { n2 = om2; k2 = oc2; } }
    m1 = n1; c1 = k1; m2 = n2; c2 = k2;
}

// ---------------- fp32 -> fp16 conversion ----------------
__global__ void cvt_kernel(const float4* __restrict__ src, size_t n4, int which) {
    __half2* dst = (which == 0) ? (__half2*)g_x16
                 : (which == 1) ? (__half2*)g_rx16
                 : (which == 2) ? (__half2*)g_w16 : (__half2*)g_rw16;
    size_t i = blockIdx.x * (size_t)blockDim.x + threadIdx.x;
    size_t st = (size_t)gridDim.x * blockDim.x;
    for (; i < n4; i += st) {
        float4 v = src[i];
        dst[2*i]   = __floats2half2_rn(v.x, v.y);
        dst[2*i+1] = __floats2half2_rn(v.z, v.w);
    }
}

// ---------------- main GEMM + online-softmax partials ----------------
struct PScr { float m1, s, m2; int c1, c2; };   // 20B, smem scratch

__global__ void __launch_bounds__(256, 1) grpo_gemm_kernel() {
    extern __shared__ char smem[];
    uint32_t sbase = smem_to_u32(smem);
    const int tid = threadIdx.x;
    const int wid = tid >> 5, lane = tid & 31;
    const int g = lane >> 2, tg = lane & 3;
    const int warp_m = wid & 3, warp_n = wid >> 2;   // 4 x 2 warp grid
    const int rt = blockIdx.x, vt = blockIdx.y;

    PScr*   pscr = (PScr*)(smem + STAGES * STAGE_BYTES);         // [2][128]
    float2* rscr = (float2*)(smem + STAGES * STAGE_BYTES);       // [2][128] (reused)

    for (int model = 0; model < 2; model++) {
        const char* Ag = (const char*)((model ? g_rx16 : g_x16) + (size_t)rt * TILE_M * Hdim);
        const char* Bg = (const char*)((model ? g_rw16 : g_w16) + (size_t)vt * TILE_N * Hdim);

        float acc[2][8][4];
        #pragma unroll
        for (int mt = 0; mt < 2; mt++)
            #pragma unroll
            for (int nt = 0; nt < 8; nt++)
                #pragma unroll
                for (int q = 0; q < 4; q++) acc[mt][nt][q] = 0.f;

        auto load_chunk = [&](int kc, int st) {
            uint32_t sa = sbase + st * STAGE_BYTES;
            uint32_t sb = sa + A_BYTES;
            const char* Ac = Ag + kc * (KC * 2);
            const char* Bc = Bg + kc * (KC * 2);
            #pragma unroll
            for (int it = 0; it < 4; it++) {
                int i = tid + it * 256;
                int r = i >> 3, q = i & 7;
                uint32_t off = (uint32_t)(r * 128 + q * 16);
                cp_async16(sa + SMEM_SWZ(off), Ac + (size_t)r * (Hdim * 2) + q * 16);
            }
            #pragma unroll
            for (int it = 0; it < 4; it++) {
                int i = tid + it * 256;
                int r = i >> 3, q = i & 7;
                uint32_t off = (uint32_t)(r * 128 + q * 16);
                cp_async16(sb + SMEM_SWZ(off), Bc + (size_t)r * (Hdim * 2) + q * 16);
            }
            CP_COMMIT();
        };

        load_chunk(0, 0);
        load_chunk(1, 1);

        for (int kc = 0; kc < NUM_KC; kc++) {
            if (kc < NUM_KC - 1) asm volatile("cp.async.wait_group 1;" ::: "memory");
            else                 asm volatile("cp.async.wait_group 0;" ::: "memory");
            __syncthreads();

            uint32_t sa = sbase + (kc % 3) * STAGE_BYTES;
            uint32_t sb = sa + A_BYTES;
            #pragma unroll
            for (int ks = 0; ks < 4; ks++) {
                uint32_t kb = (uint32_t)((ks * 16 + tg * 2) * 2);
                uint32_t a[2][4];
                #pragma unroll
                for (int mt = 0; mt < 2; mt++) {
                    uint32_t r0 = (uint32_t)((warp_m * 32 + mt * 16 + g) * 128);
                    a[mt][0] = lds_u32(sa + SMEM_SWZ(r0 + kb));
                    a[mt][1] = lds_u32(sa + SMEM_SWZ(r0 + 1024 + kb));        // +8 rows
                    a[mt][2] = lds_u32(sa + SMEM_SWZ(r0 + kb + 16));          // +8 k
                    a[mt][3] = lds_u32(sa + SMEM_SWZ(r0 + 1024 + kb + 16));
                }
                uint32_t b[8][2];
                #pragma unroll
                for (int nt = 0; nt < 8; nt++) {
                    uint32_t n0 = (uint32_t)((warp_n * 64 + nt * 8 + g) * 128);
                    b[nt][0] = lds_u32(sb + SMEM_SWZ(n0 + kb));
                    b[nt][1] = lds_u32(sb + SMEM_SWZ(n0 + kb + 16));
                }
                #pragma unroll
                for (int mt = 0; mt < 2; mt++)
                    #pragma unroll
                    for (int nt = 0; nt < 8; nt++)
                        mma16816(acc[mt][nt], a[mt][0], a[mt][1], a[mt][2], a[mt][3],
                                 b[nt][0], b[nt][1]);
            }
            if (kc + 2 < NUM_KC) load_chunk(kc + 2, (kc + 2) % 3);
        }
        __syncthreads();

        // ---- epilogue ----
        if (model == 0) {
            #pragma unroll
            for (int mt = 0; mt < 2; mt++) {
                #pragma unroll
                for (int h = 0; h < 2; h++) {
                    float m1 = -INFINITY, m2 = -INFINITY, s = 0.f;
                    int c1 = -1, c2 = -1;
                    #pragma unroll
                    for (int nt = 0; nt < 8; nt++) {
                        #pragma unroll
                        for (int c = 0; c < 2; c++) {
                            float l = acc[mt][nt][h * 2 + c];
                            int col = vt * TILE_N + warp_n * 64 + nt * 8 + tg * 2 + c;
                            if (l > m1) { s = s * __expf(m1 - l) + 1.f; m2 = m1; c2 = c1; m1 = l; c1 = col; }
                            else        { s += __expf(l - m1); if (l > m2) { m2 = l; c2 = col; } }
                        }
                    }
                    #pragma unroll
                    for (int off = 1; off <= 2; off <<= 1) {
                        float om1 = __shfl_xor_sync(0xffffffffu, m1, off);
                        float om2 = __shfl_xor_sync(0xffffffffu, m2, off);
                        float os  = __shfl_xor_sync(0xffffffffu, s,  off);
                        int   oc1 = __shfl_xor_sync(0xffffffffu, c1, off);
                        int   oc2 = __shfl_xor_sync(0xffffffffu, c2, off);
                        comb(m1, c1, m2, c2, s, om1, oc1, om2, oc2, os);
                    }
                    if (tg == 0) {
                        PScr p; p.m1 = m1; p.s = s; p.m2 = m2; p.c1 = c1; p.c2 = c2;
                        pscr[warp_n * 128 + warp_m * 32 + mt * 16 + h * 8 + g] = p;
                    }
                }
            }
            __syncthreads();
            if (tid < 128) {
                PScr p0 = pscr[tid], p1 = pscr[128 + tid];
                comb(p0.m1, p0.c1, p0.m2, p0.c2, p0.s, p1.m1, p1.c1, p1.m2, p1.c2, p1.s);
                Partial o; o.m1 = p0.m1; o.s = p0.s; o.m2 = p0.m2; o.c1 = p0.c1; o.c2 = p0.c2;
                g_part[vt][rt * TILE_M + tid] = o;
            }
            __syncthreads();
        } else {
            #pragma unroll
            for (int mt = 0; mt < 2; mt++) {
                #pragma unroll
                for (int h = 0; h < 2; h++) {
                    float rm = -INFINITY, rs = 0.f;
                    #pragma unroll
                    for (int nt = 0; nt < 8; nt++) {
                        #pragma unroll
                        for (int c = 0; c < 2; c++) {
                            float l = acc[mt][nt][h * 2 + c];
                            if (l > rm) { rs = rs * __expf(rm - l) + 1.f; rm = l; }
                            else        rs += __expf(l - rm);
                        }
                    }
                    #pragma unroll
                    for (int off = 1; off <= 2; off <<= 1) {
                        float om = __shfl_xor_sync(0xffffffffu, rm, off);
                        float os = __shfl_xor_sync(0xffffffffu, rs, off);
                        float M = fmaxf(rm, om);
                        rs = rs * __expf(rm - M) + os * __expf(om - M);
                        rm = M;
                    }
                    if (tg == 0)
                        rscr[warp_n * 128 + warp_m * 32 + mt * 16 + h * 8 + g] = make_float2(rm, rs);
                }
            }
            __syncthreads();
            if (tid < 128) {
                float2 a = rscr[tid], b = rscr[128 + tid];
                float M = fmaxf(a.x, b.x);
                float S = a.y * __expf(a.x - M) + b.y * __expf(b.x - M);
                g_rpart[vt][rt * TILE_M + tid] = make_float2(M, S);
            }
            __syncthreads();
        }
    }
}

// ---------------- reduce over vocab tiles + exact top-2 refinement ----------------
DINLINE float block_sum256(float v, float* sv, int tid) {
    sv[tid] = v; __syncthreads();
    for (int st = 128; st > 0; st >>= 1) { if (tid < st) sv[tid] += sv[tid + st]; __syncthreads(); }
    float r = sv[0]; __syncthreads(); return r;
}

__global__ void __launch_bounds__(256) reduce_refine_kernel(
    const float* __restrict__ x,  const float* __restrict__ w,
    const float* __restrict__ rx, const float* __restrict__ rw)
{
    const int row = blockIdx.x, tid = threadIdx.x;
    __shared__ float sm1[256], sm2[256], sv[256];
    __shared__ int   sc1[256], sc2[256];

    float m1 = -INFINITY, m2 = -INFINITY, rm = -INFINITY, s = 0.f, rs = 0.f;
    int c1 = -1, c2 = -1;
    if (tid < NUM_VT) {
        Partial p = g_part[tid][row];
        m1 = p.m1; m2 = p.m2; c1 = p.c1; c2 = p.c2; s = p.s;
        float2 rp = g_rpart[tid][row];
        rm = rp.x; rs = rp.y;
    }
    sm1[tid] = m1; sm2[tid] = m2; sc1[tid] = c1; sc2[tid] = c2; __syncthreads();
    for (int st = 128; st > 0; st >>= 1) {
        if (tid < st) {
            float a1 = sm1[tid], a2 = sm2[tid]; int i1 = sc1[tid], i2 = sc2[tid];
            float b1 = sm1[tid+st], b2 = sm2[tid+st]; int j1 = sc1[tid+st], j2 = sc2[tid+st];
            float o1, o2; int k1, k2;
            if (a1 >= b1) { o1 = a1; k1 = i1; if (b1 > a2) { o2 = b1; k2 = j1; } else { o2 = a2; k2 = i2; } }
            else          { o1 = b1; k1 = j1; if (a1 > b2) { o2 = a1; k2 = i1; } else { o2 = b2; k2 = j2; } }
            sm1[tid] = o1; sc1[tid] = k1; sm2[tid] = o2; sc2[tid] = k2;
        }
        __syncthreads();
    }
    float M1 = sm1[0]; int cand1 = sc1[0], cand2 = sc2[0]; __syncthreads();

    sv[tid] = rm; __syncthreads();
    for (int st = 128; st > 0; st >>= 1) { if (tid < st) sv[tid] = fmaxf(sv[tid], sv[tid+st]); __syncthreads(); }
    float RM = sv[0]; __syncthreads();

    float S  = block_sum256((tid < NUM_VT) ? s  * expf(m1 - M1) : 0.f, sv, tid);
    float RS = block_sum256((tid < NUM_VT) ? rs * expf(rm - RM) : 0.f, sv, tid);
    float lse  = M1 + logf(S);
    float rlse = RM + logf(RS);

    if (cand2 < 0) cand2 = cand1;
    const float* xr  = x  + (size_t)row * Hdim;
    const float* rxr = rx + (size_t)row * Hdim;
    const float* w1  = w  + (size_t)cand1 * Hdim;
    const float* w2  = w  + (size_t)cand2 * Hdim;
    const float* rw1 = rw + (size_t)cand1 * Hdim;
    const float* rw2 = rw + (size_t)cand2 * Hdim;
    float d0 = 0, d1 = 0, d2 = 0, d3 = 0;
    for (int i = tid; i < Hdim; i += 256) {
        float xv = xr[i], rxv = rxr[i];
        d0 += xv * w1[i];   d1 += xv * w2[i];
        d2 += rxv * rw1[i]; d3 += rxv * rw2[i];
    }
    float P1 = block_sum256(d0, sv, tid);
    float P2 = block_sum256(d1, sv, tid);
    float Q1 = block_sum256(d2, sv, tid);
    float Q2 = block_sum256(d3, sv, tid);

    if (tid == 0) {
        bool pick1 = (P1 > P2) || (P1 == P2 && cand1 <= cand2);
        float ps = pick1 ? P1 : P2;
        float qs = pick1 ? Q1 : Q2;
        double tok_lp = (double)ps - (double)lse;
        double ref_lp = (double)qs - (double)rlse;
        double d = ref_lp - tok_lp;
        g_kl[row] = (float)(exp(d) - d - 1.0);
    }
}

// ---------------- final: advantages, masked loss, mean KL ----------------
__global__ void __launch_bounds__(256) final_kernel(
    const int* __restrict__ mask, const float* __restrict__ rewards, float* __restrict__ out)
{
    __shared__ float s_adv[Bdim], s_klb[Bdim], s_mb[Bdim], s_loss, s_mask;
    const int tid = threadIdx.x;
    if (tid == 0) { s_loss = 0.f; s_mask = 0.f; }
    if (tid < Bdim) { s_klb[tid] = 0.f; s_mb[tid] = 0.f; }
    if (tid == 0) {
        float r[Bdim];
        for (int i = 0; i < Bdim; i++) r[i] = rewards[i];
        for (int gi = 0; gi < Bdim / 4; gi++) {
            float mu = 0.f;
            for (int j = 0; j < 4; j++) mu += r[gi*4+j];
            mu *= 0.25f;
            float var = 0.f;
            for (int j = 0; j < 4; j++) { float dd = r[gi*4+j] - mu; var += dd * dd; }
            float sd = sqrtf(var / 3.0f);
            for (int j = 0; j < 4; j++) s_adv[gi*4+j] = (r[gi*4+j] - mu) / (sd + 1e-4f);
        }
    }
    __syncthreads();
    float ln = 0.f, ms = 0.f;
    for (int i = tid; i < Rdim; i += blockDim.x) {
        float m = (float)mask[i];
        float k = g_kl[i];
        int b = i >> 8;
        ln += m * (s_adv[b] - 0.1f * k);
        ms += m;
        atomicAdd(&s_klb[b], m * k);
        atomicAdd(&s_mb[b], m);
    }
    atomicAdd(&s_loss, ln);
    atomicAdd(&s_mask, ms);
    __syncthreads();
    if (tid == 0) {
        out[0] = -s_loss / s_mask;
        float mk = 0.f;
        for (int b = 0; b < Bdim; b++) mk += s_klb[b] / s_mb[b];
        out[1] = mk / (float)Bdim;
    }
}

// ---------------- launcher ----------------
extern "C" void kernel_launch(void* const* d_in, const int* in_sizes, int n_in,
                              void* d_out, int out_size) {
    const float* x       = (const float*)d_in[0];
    const float* w       = (const float*)d_in[1];
    const int*   mask    = (const int*)d_in[2];
    const float* rewards = (const float*)d_in[3];
    const float* rx      = (const float*)d_in[4];
    const float* rw      = (const float*)d_in[5];

    size_t nx4 = (size_t)Rdim * Hdim / 4;
    size_t nw4 = (size_t)Vdim * Hdim / 4;
    cvt_kernel<<<1024, 256>>>((const float4*)x,  nx4, 0);
    cvt_kernel<<<1024, 256>>>((const float4*)rx, nx4, 1);
    cvt_kernel<<<2048, 256>>>((const float4*)w,  nw4, 2);
    cvt_kernel<<<2048, 256>>>((const float4*)rw, nw4, 3);

    static bool attr_set = false;
    if (!attr_set) {
        cudaFuncSetAttribute(grpo_gemm_kernel,
                             cudaFuncAttributeMaxDynamicSharedMemorySize, SMEM_TOTAL);
        attr_set = true;
    }
    grpo_gemm_kernel<<<dim3(NUM_RT, NUM_VT), 256, SMEM_TOTAL>>>();

    reduce_refine_kernel<<<Rdim, 256>>>(x, w, rx, rw);
    final_kernel<<<1, 256>>>(mask, rewards, (float*)d_out);
}

// round 3
// speedup vs baseline: 1.0198x; 1.0198x over previous
#include <cuda_runtime.h>
#include <cuda_fp16.h>
#include <cstdint>
#include <math.h>

// ---------------- problem dims ----------------
#define Hdim 2048
#define Vdim 32000
#define Bdim 8
#define Tdim 256
#define Rdim (Bdim*Tdim)          // 2048 token rows
#define TILE_M 128
#define TILE_N 256
#define KC 64                     // halves per K chunk (128 bytes per row)
#define NUM_KC (Hdim/KC)          // 32
#define NUM_RT (Rdim/TILE_M)      // 16
#define NUM_VT (Vdim/TILE_N)      // 125
#define A_BYTES (TILE_M*KC*2)     // 16384
#define B_BYTES (TILE_N*KC*2)     // 32768
#define STAGE_BYTES (A_BYTES+B_BYTES)   // 49152
#define STAGES 3
#define SCRATCH_BYTES 12288
#define SMEM_TOTAL (STAGES*STAGE_BYTES + SCRATCH_BYTES)  // 159744

#define DINLINE __device__ __forceinline__

// ---------------- device scratch (no runtime alloc allowed) ----------------
__device__ __half g_x16 [(size_t)Rdim*Hdim];
__device__ __half g_rx16[(size_t)Rdim*Hdim];
__device__ __half g_w16 [(size_t)Vdim*Hdim];
__device__ __half g_rw16[(size_t)Vdim*Hdim];

struct Partial { float m1, s, m2; int c1, c2; };           // policy per (vt,row)
__device__ Partial g_part [NUM_VT][Rdim];
__device__ float2  g_rpart[NUM_VT][Rdim];                  // ref (rm, rs)
__device__ float   g_kl[Rdim];

// ---------------- helpers ----------------
DINLINE uint32_t smem_to_u32(const void* p) {
    uint32_t a;
    asm("{ .reg .u64 t; cvta.to.shared.u64 t, %1; cvt.u32.u64 %0, t; }" : "=r"(a) : "l"(p));
    return a;
}
DINLINE uint32_t lds_u32(uint32_t addr) {
    uint32_t v;
    asm volatile("ld.shared.b32 %0, [%1];" : "=r"(v) : "r"(addr));
    return v;
}
DINLINE void cp_async16(uint32_t saddr, const void* g) {
    asm volatile("cp.async.cg.shared.global [%0], [%1], 16;" :: "r"(saddr), "l"(g) : "memory");
}
#define CP_COMMIT() asm volatile("cp.async.commit_group;" ::: "memory")
#define SMEM_SWZ(off) ((off) ^ (((off) >> 3) & 0x70))

DINLINE void mma16816(float* d, uint32_t a0, uint32_t a1, uint32_t a2, uint32_t a3,
                      uint32_t b0, uint32_t b1) {
    asm volatile(
        "mma.sync.aligned.m16n8k16.row.col.f32.f16.f16.f32 "
        "{%0,%1,%2,%3}, {%4,%5,%6,%7}, {%8,%9}, {%0,%1,%2,%3};"
        : "+f"(d[0]), "+f"(d[1]), "+f"(d[2]), "+f"(d[3])
        : "r"(a0), "r"(a1), "r"(a2), "r"(a3), "r"(b0), "r"(b1));
}

// merge two (top2 + relative sumexp) sets; "self" wins ties (lower column first)
DINLINE void comb(float& m1, int& c1, float& m2, int& c2, float& s,
                  float om1, int oc1, float om2, int oc2, float os) {
    float M = fmaxf(m1, om1);
    s = s * __expf(m1 - M) + os * __expf(om1 - M);
    float n1, n2; int k1, k2;
    if (m1 >= om1) { n1 = m1; k1 = c1; if (om1 > m2) { n2 = om1; k2 = oc1; } else { n2 = m2; k2 = c2; } }
    else           { n1 = om1; k1 = oc1; if (m1 > om2) { n2 = m1; k2 = c1; } else { n2 = om2; k2 = oc2; } }
    m1 = n1; c1 = k1; m2 = n2; c2 = k2;
}

// ---------------- fp32 -> fp16 conversion ----------------
__global__ void cvt_kernel(const float4* __restrict__ src, size_t n4, int which) {
    __half2* dst = (which == 0) ? (__half2*)g_x16
                 : (which == 1) ? (__half2*)g_rx16
                 : (which == 2) ? (__half2*)g_w16 : (__half2*)g_rw16;
    size_t i = blockIdx.x * (size_t)blockDim.x + threadIdx.x;
    size_t st = (size_t)gridDim.x * blockDim.x;
    for (; i < n4; i += st) {
        float4 v = src[i];
        dst[2*i]   = __floats2half2_rn(v.x, v.y);
        dst[2*i+1] = __floats2half2_rn(v.z, v.w);
    }
}

// ---------------- main GEMM + online-softmax partials ----------------
struct PScr { float m1, s, m2; int c1, c2; };   // 20B, smem scratch

__global__ void __launch_bounds__(256, 1) grpo_gemm_kernel() {
    extern __shared__ char smem[];
    uint32_t sbase = smem_to_u32(smem);
    const int tid = threadIdx.x;
    const int wid = tid >> 5, lane = tid & 31;
    const int g = lane >> 2, tg = lane & 3;
    const int warp_m = wid & 1, warp_n = wid >> 1;   // 2 x 4 warp grid; warp tile 64x64
    const int rt = blockIdx.x, vt = blockIdx.y;

    PScr*   pscr = (PScr*)(smem + STAGES * STAGE_BYTES);         // [4][128]
    float2* rscr = (float2*)(smem + STAGES * STAGE_BYTES);       // [4][128] (reused)

    for (int model = 0; model < 2; model++) {
        const char* Ag = (const char*)((model ? g_rx16 : g_x16) + (size_t)rt * TILE_M * Hdim);
        const char* Bg = (const char*)((model ? g_rw16 : g_w16) + (size_t)vt * TILE_N * Hdim);

        float acc[4][8][4];
        #pragma unroll
        for (int mt = 0; mt < 4; mt++)
            #pragma unroll
            for (int nt = 0; nt < 8; nt++)
                #pragma unroll
                for (int q = 0; q < 4; q++) acc[mt][nt][q] = 0.f;

        auto load_chunk = [&](int kc, int st) {
            uint32_t sa = sbase + st * STAGE_BYTES;
            uint32_t sb = sa + A_BYTES;
            const char* Ac = Ag + kc * (KC * 2);
            const char* Bc = Bg + kc * (KC * 2);
            #pragma unroll
            for (int it = 0; it < 4; it++) {        // A: 128 rows * 8 x 16B
                int i = tid + it * 256;
                int r = i >> 3, q = i & 7;
                uint32_t off = (uint32_t)(r * 128 + q * 16);
                cp_async16(sa + SMEM_SWZ(off), Ac + (size_t)r * (Hdim * 2) + q * 16);
            }
            #pragma unroll
            for (int it = 0; it < 8; it++) {        // B: 256 rows * 8 x 16B
                int i = tid + it * 256;
                int r = i >> 3, q = i & 7;
                uint32_t off = (uint32_t)(r * 128 + q * 16);
                cp_async16(sb + SMEM_SWZ(off), Bc + (size_t)r * (Hdim * 2) + q * 16);
            }
            CP_COMMIT();
        };

        load_chunk(0, 0);
        load_chunk(1, 1);

        for (int kc = 0; kc < NUM_KC; kc++) {
            if (kc < NUM_KC - 1) asm volatile("cp.async.wait_group 1;" ::: "memory");
            else                 asm volatile("cp.async.wait_group 0;" ::: "memory");
            __syncthreads();

            // issue next-next chunk loads early (stage (kc+2)%3 == stage (kc-1)%3,
            // which every warp finished reading before this iteration's syncthreads)
            if (kc + 2 < NUM_KC) load_chunk(kc + 2, (kc + 2) % 3);

            uint32_t sa = sbase + (kc % 3) * STAGE_BYTES;
            uint32_t sb = sa + A_BYTES;
            #pragma unroll
            for (int ks = 0; ks < 4; ks++) {
                uint32_t kb = (uint32_t)((ks * 16 + tg * 2) * 2);
                uint32_t a[4][4];
                #pragma unroll
                for (int mt = 0; mt < 4; mt++) {
                    uint32_t r0 = (uint32_t)((warp_m * 64 + mt * 16 + g) * 128);
                    a[mt][0] = lds_u32(sa + SMEM_SWZ(r0 + kb));
                    a[mt][1] = lds_u32(sa + SMEM_SWZ(r0 + 1024 + kb));        // +8 rows
                    a[mt][2] = lds_u32(sa + SMEM_SWZ(r0 + kb + 16));          // +8 k
                    a[mt][3] = lds_u32(sa + SMEM_SWZ(r0 + 1024 + kb + 16));
                }
                uint32_t b[8][2];
                #pragma unroll
                for (int nt = 0; nt < 8; nt++) {
                    uint32_t n0 = (uint32_t)((warp_n * 64 + nt * 8 + g) * 128);
                    b[nt][0] = lds_u32(sb + SMEM_SWZ(n0 + kb));
                    b[nt][1] = lds_u32(sb + SMEM_SWZ(n0 + kb + 16));
                }
                #pragma unroll
                for (int mt = 0; mt < 4; mt++)
                    #pragma unroll
                    for (int nt = 0; nt < 8; nt++)
                        mma16816(acc[mt][nt], a[mt][0], a[mt][1], a[mt][2], a[mt][3],
                                 b[nt][0], b[nt][1]);
            }
        }
        __syncthreads();

        // ---- epilogue ----
        if (model == 0) {
            #pragma unroll
            for (int mt = 0; mt < 4; mt++) {
                #pragma unroll
                for (int h = 0; h < 2; h++) {
                    float m1 = -INFINITY, m2 = -INFINITY, s = 0.f;
                    int c1 = -1, c2 = -1;
                    #pragma unroll
                    for (int nt = 0; nt < 8; nt++) {
                        #pragma unroll
                        for (int c = 0; c < 2; c++) {
                            float l = acc[mt][nt][h * 2 + c];
                            int col = vt * TILE_N + warp_n * 64 + nt * 8 + tg * 2 + c;
                            if (l > m1) { s = s * __expf(m1 - l) + 1.f; m2 = m1; c2 = c1; m1 = l; c1 = col; }
                            else        { s += __expf(l - m1); if (l > m2) { m2 = l; c2 = col; } }
                        }
                    }
                    #pragma unroll
                    for (int off = 1; off <= 2; off <<= 1) {
                        float om1 = __shfl_xor_sync(0xffffffffu, m1, off);
                        float om2 = __shfl_xor_sync(0xffffffffu, m2, off);
                        float os  = __shfl_xor_sync(0xffffffffu, s,  off);
                        int   oc1 = __shfl_xor_sync(0xffffffffu, c1, off);
                        int   oc2 = __shfl_xor_sync(0xffffffffu, c2, off);
                        comb(m1, c1, m2, c2, s, om1, oc1, om2, oc2, os);
                    }
                    if (tg == 0) {
                        PScr p; p.m1 = m1; p.s = s; p.m2 = m2; p.c1 = c1; p.c2 = c2;
                        pscr[warp_n * 128 + warp_m * 64 + mt * 16 + h * 8 + g] = p;
                    }
                }
            }
            __syncthreads();
            if (tid < 128) {
                PScr p0 = pscr[tid];        // warp_n=0 first -> lowest cols win ties
                #pragma unroll
                for (int wq = 1; wq < 4; wq++) {
                    PScr p1 = pscr[wq * 128 + tid];
                    comb(p0.m1, p0.c1, p0.m2, p0.c2, p0.s, p1.m1, p1.c1, p1.m2, p1.c2, p1.s);
                }
                Partial o; o.m1 = p0.m1; o.s = p0.s; o.m2 = p0.m2; o.c1 = p0.c1; o.c2 = p0.c2;
                g_part[vt][rt * TILE_M + tid] = o;
            }
            __syncthreads();
        } else {
            #pragma unroll
            for (int mt = 0; mt < 4; mt++) {
                #pragma unroll
                for (int h = 0; h < 2; h++) {
                    float rm = -INFINITY, rs = 0.f;
                    #pragma unroll
                    for (int nt = 0; nt < 8; nt++) {
                        #pragma unroll
                        for (int c = 0; c < 2; c++) {
                            float l = acc[mt][nt][h * 2 + c];
                            if (l > rm) { rs = rs * __expf(rm - l) + 1.f; rm = l; }
                            else        rs += __expf(l - rm);
                        }
                    }
                    #pragma unroll
                    for (int off = 1; off <= 2; off <<= 1) {
                        float om = __shfl_xor_sync(0xffffffffu, rm, off);
                        float os = __shfl_xor_sync(0xffffffffu, rs, off);
                        float M = fmaxf(rm, om);
                        rs = rs * __expf(rm - M) + os * __expf(om - M);
                        rm = M;
                    }
                    if (tg == 0)
                        rscr[warp_n * 128 + warp_m * 64 + mt * 16 + h * 8 + g] = make_float2(rm, rs);
                }
            }
            __syncthreads();
            if (tid < 128) {
                float2 a = rscr[tid];
                #pragma unroll
                for (int wq = 1; wq < 4; wq++) {
                    float2 b = rscr[wq * 128 + tid];
                    float M = fmaxf(a.x, b.x);
                    a.y = a.y * __expf(a.x - M) + b.y * __expf(b.x - M);
                    a.x = M;
                }
                g_rpart[vt][rt * TILE_M + tid] = a;
            }
            __syncthreads();
        }
    }
}

// ---------------- reduce over vocab tiles + exact top-2 refinement ----------------
DINLINE float block_sum256(float v, float* sv, int tid) {
    sv[tid] = v; __syncthreads();
    for (int st = 128; st > 0; st >>= 1) { if (tid < st) sv[tid] += sv[tid + st]; __syncthreads(); }
    float r = sv[0]; __syncthreads(); return r;
}

__global__ void __launch_bounds__(256) reduce_refine_kernel(
    const float* __restrict__ x,  const float* __restrict__ w,
    const float* __restrict__ rx, const float* __restrict__ rw)
{
    const int row = blockIdx.x, tid = threadIdx.x;
    __shared__ float sm1[256], sm2[256], sv[256];
    __shared__ int   sc1[256], sc2[256];

    float m1 = -INFINITY, m2 = -INFINITY, rm = -INFINITY, s = 0.f, rs = 0.f;
    int c1 = -1, c2 = -1;
    if (tid < NUM_VT) {
        Partial p = g_part[tid][row];
        m1 = p.m1; m2 = p.m2; c1 = p.c1; c2 = p.c2; s = p.s;
        float2 rp = g_rpart[tid][row];
        rm = rp.x; rs = rp.y;
    }
    sm1[tid] = m1; sm2[tid] = m2; sc1[tid] = c1; sc2[tid] = c2; __syncthreads();
    for (int st = 128; st > 0; st >>= 1) {
        if (tid < st) {
            float a1 = sm1[tid], a2 = sm2[tid]; int i1 = sc1[tid], i2 = sc2[tid];
            float b1 = sm1[tid+st], b2 = sm2[tid+st]; int j1 = sc1[tid+st], j2 = sc2[tid+st];
            float o1, o2; int k1, k2;
            if (a1 >= b1) { o1 = a1; k1 = i1; if (b1 > a2) { o2 = b1; k2 = j1; } else { o2 = a2; k2 = i2; } }
            else          { o1 = b1; k1 = j1; if (a1 > b2) { o2 = a1; k2 = i1; } else { o2 = b2; k2 = j2; } }
            sm1[tid] = o1; sc1[tid] = k1; sm2[tid] = o2; sc2[tid] = k2;
        }
        __syncthreads();
    }
    float M1 = sm1[0]; int cand1 = sc1[0], cand2 = sc2[0]; __syncthreads();

    sv[tid] = rm; __syncthreads();
    for (int st = 128; st > 0; st >>= 1) { if (tid < st) sv[tid] = fmaxf(sv[tid], sv[tid+st]); __syncthreads(); }
    float RM = sv[0]; __syncthreads();

    float S  = block_sum256((tid < NUM_VT) ? s  * expf(m1 - M1) : 0.f, sv, tid);
    float RS = block_sum256((tid < NUM_VT) ? rs * expf(rm - RM) : 0.f, sv, tid);
    float lse  = M1 + logf(S);
    float rlse = RM + logf(RS);

    if (cand2 < 0) cand2 = cand1;
    const float* xr  = x  + (size_t)row * Hdim;
    const float* rxr = rx + (size_t)row * Hdim;
    const float* w1  = w  + (size_t)cand1 * Hdim;
    const float* w2  = w  + (size_t)cand2 * Hdim;
    const float* rw1 = rw + (size_t)cand1 * Hdim;
    const float* rw2 = rw + (size_t)cand2 * Hdim;
    float d0 = 0, d1 = 0, d2 = 0, d3 = 0;
    for (int i = tid; i < Hdim; i += 256) {
        float xv = xr[i], rxv = rxr[i];
        d0 += xv * w1[i];   d1 += xv * w2[i];
        d2 += rxv * rw1[i]; d3 += rxv * rw2[i];
    }
    float P1 = block_sum256(d0, sv, tid);
    float P2 = block_sum256(d1, sv, tid);
    float Q1 = block_sum256(d2, sv, tid);
    float Q2 = block_sum256(d3, sv, tid);

    if (tid == 0) {
        bool pick1 = (P1 > P2) || (P1 == P2 && cand1 <= cand2);
        float ps = pick1 ? P1 : P2;
        float qs = pick1 ? Q1 : Q2;
        double tok_lp = (double)ps - (double)lse;
        double ref_lp = (double)qs - (double)rlse;
        double d = ref_lp - tok_lp;
        g_kl[row] = (float)(exp(d) - d - 1.0);
    }
}

// ---------------- final: advantages, masked loss, mean KL ----------------
__global__ void __launch_bounds__(256) final_kernel(
    const int* __restrict__ mask, const float* __restrict__ rewards, float* __restrict__ out)
{
    __shared__ float s_adv[Bdim], s_klb[Bdim], s_mb[Bdim], s_loss, s_mask;
    const int tid = threadIdx.x;
    if (tid == 0) { s_loss = 0.f; s_mask = 0.f; }
    if (tid < Bdim) { s_klb[tid] = 0.f; s_mb[tid] = 0.f; }
    if (tid == 0) {
        float r[Bdim];
        for (int i = 0; i < Bdim; i++) r[i] = rewards[i];
        for (int gi = 0; gi < Bdim / 4; gi++) {
            float mu = 0.f;
            for (int j = 0; j < 4; j++) mu += r[gi*4+j];
            mu *= 0.25f;
            float var = 0.f;
            for (int j = 0; j < 4; j++) { float dd = r[gi*4+j] - mu; var += dd * dd; }
            float sd = sqrtf(var / 3.0f);
            for (int j = 0; j < 4; j++) s_adv[gi*4+j] = (r[gi*4+j] - mu) / (sd + 1e-4f);
        }
    }
    __syncthreads();
    float ln = 0.f, ms = 0.f;
    for (int i = tid; i < Rdim; i += blockDim.x) {
        float m = (float)mask[i];
        float k = g_kl[i];
        int b = i >> 8;
        ln += m * (s_adv[b] - 0.1f * k);
        ms += m;
        atomicAdd(&s_klb[b], m * k);
        atomicAdd(&s_mb[b], m);
    }
    atomicAdd(&s_loss, ln);
    atomicAdd(&s_mask, ms);
    __syncthreads();
    if (tid == 0) {
        out[0] = -s_loss / s_mask;
        float mk = 0.f;
        for (int b = 0; b < Bdim; b++) mk += s_klb[b] / s_mb[b];
        out[1] = mk / (float)Bdim;
    }
}

// ---------------- launcher ----------------
extern "C" void kernel_launch(void* const* d_in, const int* in_sizes, int n_in,
                              void* d_out, int out_size) {
    const float* x       = (const float*)d_in[0];
    const float* w       = (const float*)d_in[1];
    const int*   mask    = (const int*)d_in[2];
    const float* rewards = (const float*)d_in[3];
    const float* rx      = (const float*)d_in[4];
    const float* rw      = (const float*)d_in[5];

    size_t nx4 = (size_t)Rdim * Hdim / 4;
    size_t nw4 = (size_t)Vdim * Hdim / 4;
    cvt_kernel<<<1024, 256>>>((const float4*)x,  nx4, 0);
    cvt_kernel<<<1024, 256>>>((const float4*)rx, nx4, 1);
    cvt_kernel<<<2048, 256>>>((const float4*)w,  nw4, 2);
    cvt_kernel<<<2048, 256>>>((const float4*)rw, nw4, 3);

    static bool attr_set = false;
    if (!attr_set) {
        cudaFuncSetAttribute(grpo_gemm_kernel,
                             cudaFuncAttributeMaxDynamicSharedMemorySize, SMEM_TOTAL);
        attr_set = true;
    }
    grpo_gemm_kernel<<<dim3(NUM_RT, NUM_VT), 256, SMEM_TOTAL>>>();

    reduce_refine_kernel<<<Rdim, 256>>>(x, w, rx, rw);
    final_kernel<<<1, 256>>>(mask, rewards, (float*)d_out);
}